// round 17
// baseline (speedup 1.0000x reference)
#include <cuda_runtime.h>
#include <cuda_bf16.h>
#include <cstdint>
#include <cstddef>

constexpr int Cc   = 64;
constexpr int Np   = 65536;
constexpr int Lnum = 4;
constexpr int Bn   = 2;
constexpr int FP   = 72;    // bf16 fragment pitch — conflict-free
constexpr int CP   = 136;   // cov transpose pitch

__device__ float g_feat[(size_t)Bn * Cc * Np];          // fp32, for conv_out
__device__ uint32_t g_featbf[(size_t)Bn * Np * 32];     // bf16 pairs, [b][n][c]
__device__ float g_sum[Bn * 64];
__device__ float g_Cov[Bn * 4096];
__device__ float g_T[Bn * 4096];                        // ping buffer
__device__ float g_T2[Bn * 4096];                       // pong buffer
__device__ float g_t[Bn * 64];
__device__ float g_t2[Bn * 64];
__device__ float g_S1[Bn * 64];
__device__ float g_S2[Bn * 64];
__device__ float g_afold[Bn * 64];
__device__ float g_bfold[Bn * 64];
__device__ float g_know[Bn * 4096];
__device__ float g_fsum[Bn * 64];
__device__ float g_M2[Bn * 4096];
__device__ float g_d2[Bn * 64];
__device__ float g_Wout[Bn * 1152];
__device__ float g_tb[Bn * 18];
__device__ float g_bout[Bn * 2];

typedef uint32_t u32;
__device__ __forceinline__ u32 pkbf(float hi, float lo) {
    u32 r; asm("cvt.rn.bf16x2.f32 %0, %1, %2;" : "=r"(r) : "f"(hi), "f"(lo));
    return r;
}
__device__ __forceinline__ float sigm(float x) { return 1.f / (1.f + __expf(-x)); }
__device__ __forceinline__ float wred(float v) {
#pragma unroll
    for (int o = 16; o > 0; o >>= 1) v += __shfl_xor_sync(0xffffffffu, v, o);
    return v;
}
__device__ __forceinline__ u32 smem_u32(const void* p) {
    u32 a;
    asm("{ .reg .u64 t; cvta.to.shared.u64 t, %1; cvt.u32.u64 %0, t; }"
        : "=r"(a) : "l"(p));
    return a;
}
__device__ __forceinline__ void mma16816(float c[4], u32 a0, u32 a1, u32 a2,
                                         u32 a3, u32 b0, u32 b1) {
    asm volatile(
        "mma.sync.aligned.m16n8k16.row.col.f32.bf16.bf16.f32 "
        "{%0,%1,%2,%3}, {%4,%5,%6,%7}, {%8,%9}, {%0,%1,%2,%3};"
        : "+f"(c[0]), "+f"(c[1]), "+f"(c[2]), "+f"(c[3])
        : "r"(a0), "r"(a1), "r"(a2), "r"(a3), "r"(b0), "r"(b1));
}

// ===================== init =====================
__global__ void zero_init_kernel() {
    int tid = threadIdx.x;
    for (int i = tid; i < Bn * 4096; i += 256) {
        g_Cov[i] = 0.f;
        g_T[i] = (((i >> 6) & 63) == (i & 63)) ? 1.f : 0.f;
    }
    for (int i = tid; i < Bn * 64; i += 256) { g_sum[i] = 0.f; g_t[i] = 0.f; }
}

// ===================== conv3x3 in + fused covariance =====================
__global__ void __launch_bounds__(256) conv_in_kernel(
    const float* __restrict__ x, const float* __restrict__ W,
    const float* __restrict__ bias)
{
    __shared__ float xs[2 * 3 * 258];
    __shared__ float ws[64 * 18];
    __shared__ float bsh[64];
    __shared__ float sumloc[64];
    __shared__ __nv_bfloat16 Xt[2][64 * CP];
    int b = blockIdx.y, y = blockIdx.x, tid = threadIdx.x;
    for (int i = tid; i < 64 * 18; i += 256) ws[i] = W[i];
    if (tid < 64) { bsh[tid] = bias[tid]; sumloc[tid] = 0.f; }
    for (int i = tid; i < 2 * 3 * 258; i += 256) {
        int c = i / 774, rem = i % 774, r = rem / 258, col = rem % 258;
        int yy = y + r - 1, xx = col - 1;
        float v = 0.f;
        if (yy >= 0 && yy < 256 && xx >= 0 && xx < 256)
            v = x[((size_t)(b * 2 + c) * 256 + yy) * 256 + xx];
        xs[i] = v;
    }
    __syncthreads();
    float in[18];
#pragma unroll
    for (int c = 0; c < 2; c++)
#pragma unroll
        for (int r = 0; r < 3; r++)
#pragma unroll
            for (int k = 0; k < 3; k++)
                in[c * 9 + r * 3 + k] = xs[c * 774 + r * 258 + tid + k];
    int n = y * 256 + tid;
    size_t ob = (size_t)b * Cc * Np + n;
    u32* gbf = g_featbf + (size_t)b * Np * 32 + (size_t)n * 32;
    int half = tid >> 7, pxl = tid & 127;
    __nv_bfloat16* Xh = Xt[half];
#pragma unroll
    for (int oc = 0; oc < 64; oc += 2) {
        float a0 = bsh[oc], a1 = bsh[oc + 1];
#pragma unroll
        for (int t = 0; t < 18; t++) {
            a0 += ws[oc * 18 + t] * in[t];
            a1 += ws[(oc + 1) * 18 + t] * in[t];
        }
        g_feat[ob + (size_t)oc * Np] = a0;
        g_feat[ob + (size_t)(oc + 1) * Np] = a1;
        u32 pr = pkbf(a1, a0);
        gbf[oc >> 1] = pr;
        __nv_bfloat162 h2 = *(__nv_bfloat162*)&pr;
        Xh[oc * CP + pxl] = h2.x;
        Xh[(oc + 1) * CP + pxl] = h2.y;
        float s0 = wred(a0), s1 = wred(a1);
        if ((tid & 31) == 0) {
            atomicAdd(&sumloc[oc], s0);
            atomicAdd(&sumloc[oc + 1], s1);
        }
    }
    __syncthreads();
    if (tid < 64) atomicAdd(&g_sum[b * 64 + tid], sumloc[tid]);
    int wid = tid >> 5, g = (tid & 31) >> 2, tg = tid & 3;
    int mh = wid >> 2, rb = (wid & 3) * 16;
    const __nv_bfloat16* Xc = Xt[mh];
    float C[8][4];
#pragma unroll
    for (int i = 0; i < 8; i++)
#pragma unroll
        for (int j = 0; j < 4; j++) C[i][j] = 0.f;
#pragma unroll
    for (int ks = 0; ks < 8; ks++) {
        int kb2 = ks * 16 + 2 * tg;
        u32 a0 = *(const u32*)&Xc[(rb + g) * CP + kb2];
        u32 a1 = *(const u32*)&Xc[(rb + g + 8) * CP + kb2];
        u32 a2 = *(const u32*)&Xc[(rb + g) * CP + kb2 + 8];
        u32 a3 = *(const u32*)&Xc[(rb + g + 8) * CP + kb2 + 8];
#pragma unroll
        for (int nt = 0; nt < 8; nt++) {
            u32 b0 = *(const u32*)&Xc[(nt * 8 + g) * CP + kb2];
            u32 b1 = *(const u32*)&Xc[(nt * 8 + g) * CP + kb2 + 8];
            mma16816(C[nt], a0, a1, a2, a3, b0, b1);
        }
    }
    float* cb = g_Cov + b * 4096;
    int c0 = rb + g;
#pragma unroll
    for (int nt = 0; nt < 8; nt++) {
        int d = nt * 8 + tg * 2;
        atomicAdd(&cb[c0 * 64 + d], C[nt][0]);
        atomicAdd(&cb[c0 * 64 + d + 1], C[nt][1]);
        atomicAdd(&cb[(c0 + 8) * 64 + d], C[nt][2]);
        atomicAdd(&cb[(c0 + 8) * 64 + d + 1], C[nt][3]);
    }
}

// ===================== layer-0 stats (standalone) ========================
__global__ void __launch_bounds__(256) prep_stats_kernel() {
    __shared__ float CovS[4096], Tr[512], sumS[64];
    int b = blockIdx.y, bx = blockIdx.x, tid = threadIdx.x;
    int c0 = bx * 8;
    for (int i = tid; i < 4096; i += 256) CovS[i] = g_Cov[b * 4096 + i];
    for (int i = tid; i < 512; i += 256) Tr[i] = g_T[b * 4096 + c0 * 64 + i];
    if (tid < 64) sumS[tid] = g_sum[b * 64 + tid];
    for (int i = tid; i < 512; i += 256) g_know[b * 4096 + bx * 512 + i] = 0.f;
    if (bx == 0 && tid < 64) g_fsum[b * 64 + tid] = 0.f;
    __syncthreads();
    int cl = tid >> 5, lane = tid & 31;
    const float* Tc = Tr + cl * 64;
    float rs = 0.f, qf = 0.f;
#pragma unroll
    for (int eo = 0; eo < 2; eo++) {
        int e = lane + eo * 32;
        float Te = Tc[e];
        rs += Te * sumS[e];
        const float* Ce = CovS + e * 64;
        float i0 = 0, i1 = 0, i2 = 0, i3 = 0;
#pragma unroll
        for (int f = 0; f < 64; f += 4) {
            i0 += Ce[f] * Tc[f];         i1 += Ce[f + 1] * Tc[f + 1];
            i2 += Ce[f + 2] * Tc[f + 2]; i3 += Ce[f + 3] * Tc[f + 3];
        }
        qf += Te * ((i0 + i1) + (i2 + i3));
    }
#pragma unroll
    for (int o = 16; o > 0; o >>= 1) {
        rs += __shfl_xor_sync(~0u, rs, o);
        qf += __shfl_xor_sync(~0u, qf, o);
    }
    if (lane == 0) {
        int c = c0 + cl;
        float tc = g_t[b * 64 + c];
        g_S1[b * 64 + c] = rs + 65536.f * tc;
        g_S2[b * 64 + c] = qf + 2.f * tc * rs + 65536.f * tc * tc;
    }
}

// ===================== pass 2: fused weff prologue + warp-MMA ============
constexpr int SM_WHI = 0;
constexpr int SM_WLO = 36864;
constexpr int SM_XSA = 73728;
constexpr int SM_XSB = 92160;
constexpr int SM_VT  = 110592;
constexpr int SM_KG  = 119808;
constexpr int SM_BIA = 129024;
constexpr int SM_AUX = 130048;     // af 64 + bf 64 + wvec 64
constexpr int SMEM_P2 = 130816;

__device__ __forceinline__ void prefetch_tile(u32 xsb, const u32* gbf, int n0,
                                              int tid) {
#pragma unroll
    for (int r = 0; r < 4; r++) {
        int i = tid + 256 * r;
        int px = i >> 3, wq = i & 7;
        u32 dst = xsb + px * (FP * 2) + wq * 16;
        const u32* src = gbf + (size_t)(n0 + px) * 32 + wq * 4;
        asm volatile("cp.async.cg.shared.global [%0], [%1], 16;"
                     :: "r"(dst), "l"(src));
    }
    asm volatile("cp.async.commit_group;");
}

__global__ void __launch_bounds__(256, 1) pass2_mma_kernel(
    int par, const float* __restrict__ gamma, const float* __restrict__ beta,
    const float* __restrict__ Wk, const float* __restrict__ bk,
    const float* __restrict__ Wv, const float* __restrict__ bv,
    const float* __restrict__ Wg, const float* __restrict__ bg)
{
    extern __shared__ char smc[];
    __nv_bfloat16* WHi = (__nv_bfloat16*)(smc + SM_WHI);
    __nv_bfloat16* WLo = (__nv_bfloat16*)(smc + SM_WLO);
    __nv_bfloat16* Vt  = (__nv_bfloat16*)(smc + SM_VT);
    __nv_bfloat16* Kg  = (__nv_bfloat16*)(smc + SM_KG);
    float* biasS = (float*)(smc + SM_BIA);

    int b = blockIdx.y, tid = threadIdx.x;
    int wid = tid >> 5, g = (tid & 31) >> 2, tg = tid & 3;

    // ---- prologue: compute Weff hi/lo + beff in-block ----
    {
        const float* Tsrc = par ? g_T2 : g_T;
        const float* tsrc = par ? g_t2 : g_t;
        float* aT  = (float*)(smc + SM_VT);    // 4096 f (Vt+Kg dead)
        float* Wst = (float*)(smc + SM_XSA);   // 8192 f (Xs bufs dead)
        float* afS = (float*)(smc + SM_AUX);
        float* bfS = afS + 64;
        float* wvS = afS + 128;
        if (tid < 64) {
            int gg = tid >> 3;
            float m = 0.f, q2 = 0.f;
#pragma unroll
            for (int j = 0; j < 8; j++) {
                m += g_S1[b * 64 + gg * 8 + j];
                q2 += g_S2[b * 64 + gg * 8 + j];
            }
            float inv = 1.f / (8.f * 65536.f);
            m *= inv; q2 *= inv;
            float a = gamma[tid] * rsqrtf(q2 - m * m + 1e-5f);
            float bb = beta[tid] - m * a;
            afS[tid] = a; bfS[tid] = bb;
            wvS[tid] = a * tsrc[b * 64 + tid] + bb;
            if (blockIdx.x == 0) {
                g_afold[b * 64 + tid] = a;
                g_bfold[b * 64 + tid] = bb;
            }
        }
        __syncthreads();
        for (int i = tid; i < 4096; i += 256)
            aT[i] = afS[i >> 6] * Tsrc[b * 4096 + i];
        const float* Wsrc[4] = {Wk, Wv, Wg, Wg + 4096};
        const float* bsrc[4] = {bk, bv, bg, bg + 64};
#pragma unroll 1
        for (int p = 0; p < 2; p++) {
            __syncthreads();
            for (int i = tid; i < 4096; i += 256) {
                Wst[i] = Wsrc[2 * p][i];
                Wst[4096 + i] = Wsrc[2 * p + 1][i];
            }
            __syncthreads();
            for (int j = tid; j < 8192; j += 256) {
                int ocl = j >> 6, e = j & 63, row = p * 128 + ocl;
                const float* wr = Wst + ocl * 64;
                float a0 = 0, a1 = 0, a2 = 0, a3 = 0;
#pragma unroll
                for (int c = 0; c < 64; c += 4) {
                    a0 += wr[c]     * aT[c * 64 + e];
                    a1 += wr[c + 1] * aT[(c + 1) * 64 + e];
                    a2 += wr[c + 2] * aT[(c + 2) * 64 + e];
                    a3 += wr[c + 3] * aT[(c + 3) * 64 + e];
                }
                float w = (a0 + a1) + (a2 + a3);
                __nv_bfloat16 h = __float2bfloat16(w);
                WHi[row * FP + e] = h;
                WLo[row * FP + e] = __float2bfloat16(w - __bfloat162float(h));
            }
            if (tid < 128) {
                int sl = 2 * p + (tid >> 6), ocq = tid & 63;
                const float* wr = Wst + tid * 64;
                float a0 = bsrc[sl][ocq], a1 = 0, a2 = 0, a3 = 0;
#pragma unroll
                for (int c = 0; c < 64; c += 4) {
                    a0 += wr[c] * wvS[c];         a1 += wr[c + 1] * wvS[c + 1];
                    a2 += wr[c + 2] * wvS[c + 2]; a3 += wr[c + 3] * wvS[c + 3];
                }
                biasS[p * 128 + tid] = (a0 + a1) + (a2 + a3);
            }
        }
        __syncthreads();
    }

    float Ck[4][4];
#pragma unroll
    for (int i = 0; i < 4; i++)
#pragma unroll
        for (int j = 0; j < 4; j++) Ck[i][j] = 0.f;
    float fpart[2] = {0.f, 0.f};

    const u32* gbf = g_featbf + (size_t)b * Np * 32;
    int mtk = wid >> 1, ntb = (wid & 1) * 4;
    int rA = (wid < 4) ? wid * 16 : 64 + (wid - 4) * 16;
    int rB = (wid < 4) ? 192 + wid * 16 : 128 + (wid - 4) * 16;
    bool fwarp = (wid >= 4);

    u32 xsbase[2] = {smem_u32(smc + SM_XSA), smem_u32(smc + SM_XSB)};
    __nv_bfloat16* xsptr[2] = {(__nv_bfloat16*)(smc + SM_XSA),
                               (__nv_bfloat16*)(smc + SM_XSB)};
    prefetch_tile(xsbase[0], gbf, blockIdx.x << 7, tid);
    int bufc = 0;

    for (int t = blockIdx.x; t < 512; t += 74) {
        asm volatile("cp.async.wait_group 0;" ::: "memory");
        __syncthreads();
        int tn = t + 74;
        if (tn < 512) prefetch_tile(xsbase[bufc ^ 1], gbf, tn << 7, tid);
        const __nv_bfloat16* Xs = xsptr[bufc];

#pragma unroll 1
        for (int h = 0; h < 2; h++) {
            const __nv_bfloat16* Xh = Xs + h * 64 * FP;
            float C[2][8][4];
#pragma unroll
            for (int mt = 0; mt < 2; mt++)
#pragma unroll
                for (int nt = 0; nt < 8; nt++)
#pragma unroll
                    for (int q = 0; q < 4; q++) C[mt][nt][q] = 0.f;
#pragma unroll
            for (int ks = 0; ks < 4; ks++) {
                int kb2 = ks * 16 + 2 * tg;
                u32 bfr[8][2];
#pragma unroll
                for (int nt = 0; nt < 8; nt++) {
                    bfr[nt][0] = *(const u32*)&Xh[(nt * 8 + g) * FP + kb2];
                    bfr[nt][1] = *(const u32*)&Xh[(nt * 8 + g) * FP + kb2 + 8];
                }
#pragma unroll
                for (int mt = 0; mt < 2; mt++) {
                    int r = mt ? rB : rA;
                    u32 h0 = *(const u32*)&WHi[(r + g) * FP + kb2];
                    u32 h1 = *(const u32*)&WHi[(r + g + 8) * FP + kb2];
                    u32 h2 = *(const u32*)&WHi[(r + g) * FP + kb2 + 8];
                    u32 h3 = *(const u32*)&WHi[(r + g + 8) * FP + kb2 + 8];
#pragma unroll
                    for (int nt = 0; nt < 8; nt++)
                        mma16816(C[mt][nt], h0, h1, h2, h3, bfr[nt][0], bfr[nt][1]);
                    if (!(fwarp && mt == 1)) {   // f-gate rows: hi-only
                        u32 l0 = *(const u32*)&WLo[(r + g) * FP + kb2];
                        u32 l1 = *(const u32*)&WLo[(r + g + 8) * FP + kb2];
                        u32 l2 = *(const u32*)&WLo[(r + g) * FP + kb2 + 8];
                        u32 l3 = *(const u32*)&WLo[(r + g + 8) * FP + kb2 + 8];
#pragma unroll
                        for (int nt = 0; nt < 8; nt++)
                            mma16816(C[mt][nt], l0, l1, l2, l3, bfr[nt][0], bfr[nt][1]);
                    }
                }
            }
            if (wid < 4) {
                int r0 = rA + g, r1 = r0 + 8;
                float bk0 = biasS[r0], bk1 = biasS[r1];
                float bi0 = biasS[rB + g], bi1 = biasS[rB + g + 8];
#pragma unroll
                for (int nt = 0; nt < 8; nt++) {
                    int col = nt * 8 + tg * 2;
                    *(u32*)&Kg[r0 * FP + col] =
                        pkbf((C[0][nt][1] + bk0) * sigm(C[1][nt][1] + bi0),
                             (C[0][nt][0] + bk0) * sigm(C[1][nt][0] + bi0));
                    *(u32*)&Kg[r1 * FP + col] =
                        pkbf((C[0][nt][3] + bk1) * sigm(C[1][nt][3] + bi1),
                             (C[0][nt][2] + bk1) * sigm(C[1][nt][2] + bi1));
                }
            } else {
                int v0 = rA - 64 + g, v1 = v0 + 8;
                float bv0 = biasS[rA + g], bv1 = biasS[rA + g + 8];
                float bf0 = biasS[rB + g], bf1 = biasS[rB + g + 8];
#pragma unroll
                for (int nt = 0; nt < 8; nt++) {
                    int col = nt * 8 + tg * 2;
                    *(u32*)&Vt[v0 * FP + col] = pkbf(C[0][nt][1] + bv0, C[0][nt][0] + bv0);
                    *(u32*)&Vt[v1 * FP + col] = pkbf(C[0][nt][3] + bv1, C[0][nt][2] + bv1);
                    fpart[0] += sigm(C[1][nt][0] + bf0) + sigm(C[1][nt][1] + bf0);
                    fpart[1] += sigm(C[1][nt][2] + bf1) + sigm(C[1][nt][3] + bf1);
                }
            }
            __syncthreads();
#pragma unroll
            for (int ks = 0; ks < 4; ks++) {
                int kb2 = ks * 16 + 2 * tg;
                u32 a0 = *(const u32*)&Kg[(mtk * 16 + g) * FP + kb2];
                u32 a1 = *(const u32*)&Kg[(mtk * 16 + g + 8) * FP + kb2];
                u32 a2 = *(const u32*)&Kg[(mtk * 16 + g) * FP + kb2 + 8];
                u32 a3 = *(const u32*)&Kg[(mtk * 16 + g + 8) * FP + kb2 + 8];
#pragma unroll
                for (int ntl = 0; ntl < 4; ntl++) {
                    u32 b0 = *(const u32*)&Vt[((ntb + ntl) * 8 + g) * FP + kb2];
                    u32 b1 = *(const u32*)&Vt[((ntb + ntl) * 8 + g) * FP + kb2 + 8];
                    mma16816(Ck[ntl], a0, a1, a2, a3, b0, b1);
                }
            }
            __syncthreads();
        }
        bufc ^= 1;
    }
    float* kbase = g_know + b * 4096;
#pragma unroll
    for (int ntl = 0; ntl < 4; ntl++) {
        int c0 = mtk * 16 + g, d0 = (ntb + ntl) * 8 + tg * 2;
        atomicAdd(&kbase[c0 * 64 + d0],           Ck[ntl][0]);
        atomicAdd(&kbase[c0 * 64 + d0 + 1],       Ck[ntl][1]);
        atomicAdd(&kbase[(c0 + 8) * 64 + d0],     Ck[ntl][2]);
        atomicAdd(&kbase[(c0 + 8) * 64 + d0 + 1], Ck[ntl][3]);
    }
    if (wid >= 4) {
#pragma unroll
        for (int s = 0; s < 2; s++) {
            float v = fpart[s];
            v += __shfl_xor_sync(0xffffffffu, v, 1);
            v += __shfl_xor_sync(0xffffffffu, v, 2);
            if (tg == 0)
                atomicAdd(&g_fsum[b * 64 + (wid - 4) * 16 + g + s * 8], v);
        }
    }
}

// ===================== updA: mem + T1/M2 e-slice + d2 ====================
__global__ void __launch_bounds__(256) updA_kernel(
    const float* __restrict__ hidden, const float* __restrict__ Wq,
    const float* __restrict__ bq, const float* __restrict__ Wp,
    const float* __restrict__ bp, float* __restrict__ hid_out)
{
    __shared__ float memS[4096], WS[4096], T1L[512];
    __shared__ float fm[64], bf[64], uS[64], rSs[64], afS[8];
    int b = blockIdx.y, bx = blockIdx.x, tid = threadIdx.x;
    int e0 = bx * 8;
    if (tid < 64) {
        fm[tid] = g_fsum[b * 64 + tid] * (1.f / 65536.f);
        bf[tid] = g_bfold[b * 64 + tid];
    }
    if (tid < 8) afS[tid] = g_afold[b * 64 + e0 + tid];
    __syncthreads();
    const float* kb = g_know + b * 4096;
    const float* hb = hidden + (size_t)b * Lnum * 4096;
    float* ho = hid_out + (size_t)b * Lnum * 4096;
    for (int i = tid; i < 4096; i += 256) {
        int c = i >> 6;
        float m = fm[c] * hb[i] + kb[i] * (1.f / 65536.f);
        memS[i] = m;
        WS[i] = Wq[i];
        if (bx == 0) ho[i] = m;
    }
    __syncthreads();
    if (bx == 0 && tid < 64) {
        const float* wr = WS + tid * 64;
        float a0 = bq[tid], a1 = 0, a2 = 0, a3 = 0;
#pragma unroll
        for (int e = 0; e < 64; e += 4) {
            a0 += wr[e] * bf[e];         a1 += wr[e + 1] * bf[e + 1];
            a2 += wr[e + 2] * bf[e + 2]; a3 += wr[e + 3] * bf[e + 3];
        }
        uS[tid] = (a0 + a1) + (a2 + a3);
    }
    __syncthreads();
    if (bx == 0 && tid < 64) {
        float a0 = 0, a1 = 0, a2 = 0, a3 = 0;
#pragma unroll
        for (int c = 0; c < 64; c += 4) {
            a0 += memS[c * 64 + tid] * uS[c];
            a1 += memS[(c + 1) * 64 + tid] * uS[c + 1];
            a2 += memS[(c + 2) * 64 + tid] * uS[c + 2];
            a3 += memS[(c + 3) * 64 + tid] * uS[c + 3];
        }
        rSs[tid] = (a0 + a1) + (a2 + a3);
    }
    for (int i = tid; i < 512; i += 256) {
        int d = i >> 3, el = i & 7, e = e0 + el;
        float a0 = 0, a1 = 0, a2 = 0, a3 = 0;
#pragma unroll
        for (int c = 0; c < 64; c += 4) {
            a0 += memS[c * 64 + d] * WS[c * 64 + e];
            a1 += memS[(c + 1) * 64 + d] * WS[(c + 1) * 64 + e];
            a2 += memS[(c + 2) * 64 + d] * WS[(c + 2) * 64 + e];
            a3 += memS[(c + 3) * 64 + d] * WS[(c + 3) * 64 + e];
        }
        T1L[i] = ((a0 + a1) + (a2 + a3)) * afS[el];
    }
    __syncthreads();
    for (int i = tid; i < 4096; i += 256) WS[i] = Wp[i];
    __syncthreads();
    const float scale = 0.125f;
    for (int i = tid; i < 512; i += 256) {
        int el = i >> 6, o = i & 63;
        const float* wr = WS + o * 64;
        float a0 = 0, a1 = 0, a2 = 0, a3 = 0;
#pragma unroll
        for (int d = 0; d < 64; d += 4) {
            a0 += wr[d] * T1L[d * 8 + el];
            a1 += wr[d + 1] * T1L[(d + 1) * 8 + el];
            a2 += wr[d + 2] * T1L[(d + 2) * 8 + el];
            a3 += wr[d + 3] * T1L[(d + 3) * 8 + el];
        }
        g_M2[b * 4096 + (e0 + el) * 64 + o] = ((a0 + a1) + (a2 + a3)) * scale;
    }
    if (bx == 0 && tid < 64) {
        const float* wr = WS + tid * 64;
        float a0 = 0, a1 = 0, a2 = 0, a3 = 0;
#pragma unroll
        for (int d = 0; d < 64; d += 4) {
            a0 += wr[d] * rSs[d];         a1 += wr[d + 1] * rSs[d + 1];
            a2 += wr[d + 2] * rSs[d + 2]; a3 += wr[d + 3] * rSs[d + 3];
        }
        g_d2[b * 64 + tid] = ((a0 + a1) + (a2 + a3)) * scale + bp[tid];
    }
}

// ===================== updB: compose + next-layer stats + zero ===========
__global__ void __launch_bounds__(256) updB_kernel(int par) {
    const float* Tsrc = par ? g_T2 : g_T;
    float* Tdst       = par ? g_T  : g_T2;
    const float* tsrc = par ? g_t2 : g_t;
    float* tdst       = par ? g_t  : g_t2;
    __shared__ float A[4096], M2S[4096], Tr[512], tnewS[8], sumS[64];
    int b = blockIdx.y, bx = blockIdx.x, tid = threadIdx.x;
    int c0 = bx * 8;
    for (int i = tid; i < 4096; i += 256) {
        A[i] = Tsrc[b * 4096 + i];
        M2S[i] = g_M2[b * 4096 + i];
    }
    for (int i = tid; i < 512; i += 256) g_know[b * 4096 + bx * 512 + i] = 0.f;
    if (bx == 0 && tid < 64) g_fsum[b * 64 + tid] = 0.f;
    if (tid < 64) sumS[tid] = g_sum[b * 64 + tid];
    __syncthreads();
    for (int i = tid; i < 512; i += 256) {
        int cl = i >> 6, e = i & 63, c = c0 + cl;
        float a0 = A[c * 64 + e], a1 = 0, a2 = 0, a3 = 0;
#pragma unroll
        for (int m = 0; m < 64; m += 4) {
            a0 += M2S[m * 64 + c] * A[m * 64 + e];
            a1 += M2S[(m + 1) * 64 + c] * A[(m + 1) * 64 + e];
            a2 += M2S[(m + 2) * 64 + c] * A[(m + 2) * 64 + e];
            a3 += M2S[(m + 3) * 64 + c] * A[(m + 3) * 64 + e];
        }
        float v = (a0 + a1) + (a2 + a3);
        Tr[i] = v;
        Tdst[b * 4096 + c * 64 + e] = v;
    }
    if (tid < 8) {
        int c = c0 + tid;
        float a0 = tsrc[b * 64 + c] + g_d2[b * 64 + c], a1 = 0, a2 = 0, a3 = 0;
#pragma unroll
        for (int e = 0; e < 64; e += 4) {
            a0 += M2S[e * 64 + c] * tsrc[b * 64 + e];
            a1 += M2S[(e + 1) * 64 + c] * tsrc[b * 64 + e + 1];
            a2 += M2S[(e + 2) * 64 + c] * tsrc[b * 64 + e + 2];
            a3 += M2S[(e + 3) * 64 + c] * tsrc[b * 64 + e + 3];
        }
        float v = (a0 + a1) + (a2 + a3);
        tnewS[tid] = v;
        tdst[b * 64 + c] = v;
    }
    __syncthreads();
    for (int i = tid; i < 4096; i += 256) A[i] = g_Cov[b * 4096 + i];
    __syncthreads();
    int cl = tid >> 5, lane = tid & 31;
    const float* Tc = Tr + cl * 64;
    float rs = 0.f, qf = 0.f;
#pragma unroll
    for (int eo = 0; eo < 2; eo++) {
        int e = lane + eo * 32;
        float Te = Tc[e];
        rs += Te * sumS[e];
        const float* Ce = A + e * 64;
        float i0 = 0, i1 = 0, i2 = 0, i3 = 0;
#pragma unroll
        for (int f = 0; f < 64; f += 4) {
            i0 += Ce[f] * Tc[f];         i1 += Ce[f + 1] * Tc[f + 1];
            i2 += Ce[f + 2] * Tc[f + 2]; i3 += Ce[f + 3] * Tc[f + 3];
        }
        qf += Te * ((i0 + i1) + (i2 + i3));
    }
#pragma unroll
    for (int o = 16; o > 0; o >>= 1) {
        rs += __shfl_xor_sync(~0u, rs, o);
        qf += __shfl_xor_sync(~0u, qf, o);
    }
    if (lane == 0) {
        int c = c0 + cl;
        float tc = tnewS[cl];
        g_S1[b * 64 + c] = rs + 65536.f * tc;
        g_S2[b * 64 + c] = qf + 2.f * tc * rs + 65536.f * tc * tc;
    }
}

// ===================== conv_out prep + conv_out =========================
__global__ void __launch_bounds__(256) convout_prep_kernel(
    const float* __restrict__ W, const float* __restrict__ bias)
{
    int b = blockIdx.x, tid = threadIdx.x;
    __shared__ float T[4096];
    for (int i = tid; i < 4096; i += 256) T[i] = g_T[b * 4096 + i];
    __syncthreads();
    for (int j = tid; j < 1152; j += 256) {
        int o = j / 576, r = j % 576, e = r / 9, tap = r % 9;
        float a0 = 0, a1 = 0, a2 = 0, a3 = 0;
#pragma unroll
        for (int c = 0; c < 64; c += 4) {
            a0 += W[o * 576 + c * 9 + tap] * T[c * 64 + e];
            a1 += W[o * 576 + (c + 1) * 9 + tap] * T[(c + 1) * 64 + e];
            a2 += W[o * 576 + (c + 2) * 9 + tap] * T[(c + 2) * 64 + e];
            a3 += W[o * 576 + (c + 3) * 9 + tap] * T[(c + 3) * 64 + e];
        }
        g_Wout[b * 1152 + j] = (a0 + a1) + (a2 + a3);
    }
    if (tid < 18) {
        int o = tid / 9, tap = tid % 9;
        float acc = 0.f;
        for (int c = 0; c < 64; c++)
            acc += W[o * 576 + c * 9 + tap] * g_t[b * 64 + c];
        g_tb[b * 18 + tid] = acc;
    }
    if (tid < 2) g_bout[b * 2 + tid] = bias[tid];
}

__global__ void __launch_bounds__(256) conv_out_kernel(
    const float* __restrict__ x, float* __restrict__ out)
{
    __shared__ float fs[8 * 3 * 258];
    __shared__ float ws[1152];
    __shared__ float tb[18];
    int b = blockIdx.y, y = blockIdx.x, tid = threadIdx.x;
    for (int i = tid; i < 1152; i += 256) ws[i] = g_Wout[b * 1152 + i];
    if (tid < 18) tb[tid] = g_tb[b * 18 + tid];
    __syncthreads();
    float acc0 = g_bout[b * 2 + 0], acc1 = g_bout[b * 2 + 1];
#pragma unroll
    for (int r = 0; r < 3; r++) {
        int yy = y + r - 1;
        if (yy < 0 || yy >= 256) continue;
#pragma unroll
        for (int k = 0; k < 3; k++) {
            int xx = tid + k - 1;
            if (xx < 0 || xx >= 256) continue;
            acc0 += tb[r * 3 + k];
            acc1 += tb[9 + r * 3 + k];
        }
    }
    const float* fb = g_feat + (size_t)b * Cc * Np;
    for (int cc = 0; cc < 64; cc += 8) {
        __syncthreads();
        for (int i = tid; i < 6192; i += 256) {
            int c = i / 774, rem = i % 774, r = rem / 258, col = rem % 258;
            int yy = y + r - 1, xx = col - 1;
            float v = 0.f;
            if (yy >= 0 && yy < 256 && xx >= 0 && xx < 256)
                v = fb[(size_t)(cc + c) * Np + yy * 256 + xx];
            fs[i] = v;
        }
        __syncthreads();
#pragma unroll
        for (int c = 0; c < 8; c++) {
            float in[9];
#pragma unroll
            for (int r = 0; r < 3; r++)
#pragma unroll
                for (int k = 0; k < 3; k++)
                    in[r * 3 + k] = fs[c * 774 + r * 258 + tid + k];
            const float* w0 = &ws[(cc + c) * 9];
            const float* w1 = &ws[(64 + cc + c) * 9];
#pragma unroll
            for (int t = 0; t < 9; t++) { acc0 += w0[t] * in[t]; acc1 += w1[t] * in[t]; }
        }
    }
    int o = y * 256 + tid;
    out[(size_t)(b * 2 + 0) * Np + o] = acc0 + x[(size_t)(b * 2 + 0) * Np + o];
    out[(size_t)(b * 2 + 1) * Np + o] = acc1 + x[(size_t)(b * 2 + 1) * Np + o];
}

extern "C" void kernel_launch(void* const* d_in, const int* in_sizes, int n_in,
                              void* d_out, int out_size)
{
    const float* x      = (const float*)d_in[0];
    const float* hidden = (const float*)d_in[1];
    const float* W_in   = (const float*)d_in[2];
    const float* b_in   = (const float*)d_in[3];
    const float* gamma  = (const float*)d_in[4];
    const float* beta   = (const float*)d_in[5];
    const float* Wq     = (const float*)d_in[6];
    const float* bq     = (const float*)d_in[7];
    const float* Wk     = (const float*)d_in[8];
    const float* bk     = (const float*)d_in[9];
    const float* Wv     = (const float*)d_in[10];
    const float* bv     = (const float*)d_in[11];
    const float* Wg     = (const float*)d_in[12];
    const float* bg     = (const float*)d_in[13];
    const float* Wp     = (const float*)d_in[14];
    const float* bp     = (const float*)d_in[15];
    const float* W_out  = (const float*)d_in[16];
    const float* b_out  = (const float*)d_in[17];
    float* out = (float*)d_out;
    float* hid_out = out + 262144;

    cudaFuncSetAttribute(pass2_mma_kernel,
                         cudaFuncAttributeMaxDynamicSharedMemorySize, SMEM_P2);

    zero_init_kernel<<<1, 256>>>();
    conv_in_kernel<<<dim3(256, 2), 256>>>(x, W_in, b_in);
    prep_stats_kernel<<<dim3(8, 2), 256>>>();
    for (int l = 0; l < Lnum; l++) {
        int par = l & 1;
        pass2_mma_kernel<<<dim3(74, 2), 256, SMEM_P2>>>(
            par, gamma + l * 64, beta + l * 64,
            Wk + l * 4096, bk + l * 64, Wv + l * 4096, bv + l * 64,
            Wg + l * 8192, bg + l * 128);
        updA_kernel<<<dim3(8, 2), 256>>>(hidden + l * 4096, Wq + l * 4096,
                                         bq + l * 64, Wp + l * 4096,
                                         bp + l * 64, hid_out + l * 4096);
        updB_kernel<<<dim3(8, 2), 256>>>(par);
    }
    convout_prep_kernel<<<2, 256>>>(W_out, b_out);
    conv_out_kernel<<<dim3(256, 2), 256>>>(x, out);
}